// round 6
// baseline (speedup 1.0000x reference)
#include <cuda_runtime.h>
#include <cstdint>

// Problem constants: B=2, N=65536, M=8192, K=32
// TOTAL_GIBS=64 (16 cy, 16 cone, 16 disk, 16 ellip), NUM_OBSERVERS=16
#define EPSV 1e-8f
#define LOG2E_F 1.4426950408889634f

constexpr int Bc = 2;
constexpr int Nc = 65536;
constexpr int Mc = 8192;
constexpr int Kc = 32;
constexpr int NQ = Bc * Mc;                 // 16384 queries
constexpr int WARPS_PER_BLOCK = 8;
constexpr int THREADS = WARPS_PER_BLOCK * 32;
constexpr int Q_PER_WARP = 2;
constexpr int Q_PER_BLOCK = WARPS_PER_BLOCK * Q_PER_WARP;   // 16
constexpr int GRID_BLOCKS = NQ / Q_PER_BLOCK;               // 1024
constexpr int RPAD = 68;                    // padded row stride (words)
constexpr int KP = Kc + 1;                  // view stride pad: 528B -> disjoint banks

__device__ __forceinline__ float ex2f(float x) {
    float r; asm("ex2.approx.ftz.f32 %0, %1;" : "=f"(r) : "f"(x)); return r;
}
__device__ __forceinline__ float sqrtaf(float x) {
    float r; asm("sqrt.approx.ftz.f32 %0, %1;" : "=f"(r) : "f"(x)); return r;
}

__global__ __launch_bounds__(THREADS, 5)
void gib_kernel(const float* __restrict__ points,
                const float* __restrict__ q_coords,
                const int*   __restrict__ support_idxs,
                const float* __restrict__ cy_p,
                const float* __restrict__ cone_p,
                const float* __restrict__ disk_p,
                const float* __restrict__ ellip_p,
                const float* __restrict__ lambdas,
                float* __restrict__ out)
{
    // per-warp, per-query monomial data, 2 half-warp views (PADDED stride KP):
    //   view0 (lanes 0-15, cyl+disk):  (r4, r2, rz2, r2)
    //   view1 (lanes 16-31, cone+ell): (r2, srz, rz2, rx2)
    // view1 base = view0 + KP*16 = 528B -> bank groups of the two half-warp
    // broadcast addresses are disjoint (4-bank shift) -> conflict-free LDS.128.
    __shared__ float4 sPts[WARPS_PER_BLOCK][Q_PER_WARP][2][KP];
    __shared__ float  lamT[16 * RPAD];           // lamT[j][g] = lambdas[g][j]/K
    __shared__ float  meanS[Q_PER_BLOCK * RPAD]; // meanS[qq][g]

    const int tid   = threadIdx.x;
    const int lane  = tid & 31;
    const int wslot = tid >> 5;
    const int qbase = blockIdx.x * Q_PER_BLOCK;
    const int qA    = qbase + wslot * 2;

    // ---- cooperative transposed lambda load (once per block) ----
    {
        const float invK = 1.f / (float)Kc;
        #pragma unroll
        for (int i = tid; i < 64 * 16; i += THREADS) {
            int g = i >> 4, j = i & 15;
            lamT[j * RPAD + g] = lambdas[i] * invK;
        }
    }

    // ---- per-lane gib constants: fully uniform affine forms ----
    // quad gib (g0=lane):  arg0 = c1*v.x + c2*v.y + c3*v.z + c0
    // lin  gib (g1=l+32):  arg1 = e1*v.w + e2*v.x + e3*v.z
    float c0, c1, c2, c3, e1, e2, e3;
    if (lane < 16) {
        // cylinder: -(r2-a^2)^2*inv = -inv*r4 + 2a^2*inv*r2 - a^4*inv
        float a  = cy_p[lane * 2 + 0];
        float sg = cy_p[lane * 2 + 1];
        float inv = LOG2E_F / (2.f * sg * sg + EPSV);
        float a2 = a * a;
        c1 = -inv;
        c2 = 2.f * a2 * inv;
        c3 = 0.f;
        c0 = -a2 * a2 * inv;
        // disk: e1 on r2 (v.w), e3 on rz2 (v.z)
        float d0 = disk_p[lane * 2 + 0];
        float d1 = disk_p[lane * 2 + 1];
        e1 = -LOG2E_F / (d0 * d0 + EPSV);
        e2 = 0.f;
        e3 = -LOG2E_F / (d1 * d1 + EPSV);
    } else {
        // cone: -(s-a*rz)^2*inv, s^2 = r2+EPS exactly:
        //   = -inv*r2 + 2a*inv*srz - a^2*inv*rz2 - inv*EPS
        int j = lane - 16;
        float a  = cone_p[j * 2 + 0];
        float sg = cone_p[j * 2 + 1];
        float inv = LOG2E_F / (2.f * sg * sg + EPSV);
        c1 = -inv;
        c2 = 2.f * a * inv;
        c3 = -a * a * inv;
        c0 = -EPSV * inv;
        // ellip: qx*rx2 + qy*ry2 + qz*rz2 = (qx-qy)*rx2 + qy*r2 + qz*rz2
        float x0 = ellip_p[j * 3 + 0];
        float x1 = ellip_p[j * 3 + 1];
        float x2 = ellip_p[j * 3 + 2];
        float qx = -LOG2E_F / (x0 * x0 + EPSV);
        float qy = -LOG2E_F / (x1 * x1 + EPSV);
        float qz = -LOG2E_F / (x2 * x2 + EPSV);
        e1 = qx - qy;   // on rx2 (v.w)
        e2 = qy;        // on r2  (v.x)
        e3 = qz;        // on rz2 (v.z)
    }

    // ---- gather: lane k loads support point k for both queries ----
    #pragma unroll
    for (int qq = 0; qq < Q_PER_WARP; qq++) {
        int q = qA + qq;
        const float* qc = q_coords + q * 3;
        float qx = __ldg(qc + 0);
        float qy = __ldg(qc + 1);
        float qz = __ldg(qc + 2);
        int   idx = __ldg(support_idxs + q * Kc + lane);
        int   b   = q >> 13;                 // q / Mc
        const float* p = points + ((size_t)(b * Nc + idx)) * 3;
        float rx = __ldg(p + 0) - qx;
        float ry = __ldg(p + 1) - qy;
        float rz = __ldg(p + 2) - qz;
        float rx2 = rx * rx;
        float r2  = fmaf(ry, ry, rx2);
        float rz2 = rz * rz;
        float r4  = r2 * r2;
        float s   = sqrtaf(r2 + EPSV);
        float srz = s * rz;
        sPts[wslot][qq][0][lane] = make_float4(r4, r2,  rz2, r2);
        sPts[wslot][qq][1][lane] = make_float4(r2, srz, rz2, rx2);
    }
    __syncwarp();

    const int half = lane >> 4;
    const float4* vA = sPts[wslot][0][half];
    const float4* vB = sPts[wslot][1][half];

    float acc0A = 0.f, acc1A = 0.f, acc0B = 0.f, acc1B = 0.f;
    #pragma unroll 8
    for (int k = 0; k < Kc; k++) {
        float4 a = vA[k];                    // LDS.128 broadcast, conflict-free
        float4 b = vB[k];

        float arg0A = fmaf(c1, a.x, fmaf(c2, a.y, fmaf(c3, a.z, c0)));
        float arg0B = fmaf(c1, b.x, fmaf(c2, b.y, fmaf(c3, b.z, c0)));
        float arg1A = fmaf(e1, a.w, fmaf(e2, a.x, e3 * a.z));
        float arg1B = fmaf(e1, b.w, fmaf(e2, b.x, e3 * b.z));

        acc0A += ex2f(arg0A);
        acc0B += ex2f(arg0B);
        acc1A += ex2f(arg1A);
        acc1B += ex2f(arg1B);
    }

    // publish the 64 gib means for both queries
    {
        int qqA = wslot * 2, qqB = qqA + 1;
        meanS[qqA * RPAD + lane]      = acc0A;
        meanS[qqA * RPAD + lane + 32] = acc1A;
        meanS[qqB * RPAD + lane]      = acc0B;
        meanS[qqB * RPAD + lane + 32] = acc1B;
    }
    __syncthreads();

    // ---- block-cooperative epilogue: 16 queries x 16 observers ----
    {
        int qq = tid >> 4;
        int j  = tid & 15;
        const float4* mrow = reinterpret_cast<const float4*>(&meanS[qq * RPAD]);
        const float4* lrow = reinterpret_cast<const float4*>(&lamT[j * RPAD]);
        float acc = 0.f;
        #pragma unroll
        for (int g4 = 0; g4 < 16; g4++) {
            float4 m = mrow[g4];
            float4 l = lrow[g4];
            acc += m.x * l.x + m.y * l.y + m.z * l.z + m.w * l.w;
        }
        out[(size_t)(qbase + qq) * 16 + j] = acc;   // fully coalesced
    }
}

extern "C" void kernel_launch(void* const* d_in, const int* in_sizes, int n_in,
                              void* d_out, int out_size)
{
    // metadata order: points, q_coords, support_idxs, mc_points (unused),
    //                 cy_params, cone_params, disk_params, ellip_params, lambdas
    const float* points       = (const float*)d_in[0];
    const float* q_coords     = (const float*)d_in[1];
    const int*   support_idxs = (const int*)  d_in[2];
    const float* cy_params    = (const float*)d_in[4];
    const float* cone_params  = (const float*)d_in[5];
    const float* disk_params  = (const float*)d_in[6];
    const float* ellip_params = (const float*)d_in[7];
    const float* lambdas      = (const float*)d_in[8];
    float* out = (float*)d_out;

    gib_kernel<<<GRID_BLOCKS, THREADS>>>(points, q_coords, support_idxs,
                                         cy_params, cone_params, disk_params,
                                         ellip_params, lambdas, out);
}

// round 7
// speedup vs baseline: 1.0017x; 1.0017x over previous
#include <cuda_runtime.h>
#include <cstdint>

// Problem constants: B=2, N=65536, M=8192, K=32
// TOTAL_GIBS=64 (16 cy, 16 cone, 16 disk, 16 ellip), NUM_OBSERVERS=16
#define EPSV 1e-8f
#define LOG2E_F 1.4426950408889634f

constexpr int Bc = 2;
constexpr int Nc = 65536;
constexpr int Mc = 8192;
constexpr int Kc = 32;
constexpr int NQ = Bc * Mc;                 // 16384 queries
constexpr int WARPS_PER_BLOCK = 8;
constexpr int THREADS = WARPS_PER_BLOCK * 32;
constexpr int Q_PER_WARP = 2;
constexpr int Q_PER_BLOCK = WARPS_PER_BLOCK * Q_PER_WARP;   // 16
constexpr int GRID_BLOCKS = NQ / Q_PER_BLOCK;               // 1024
constexpr int RPAD = 68;                    // meanS row stride (words), 272B = 17*16B
constexpr int KP = Kc + 1;                  // sPts row pad

__device__ __forceinline__ float ex2f(float x) {
    float r; asm("ex2.approx.ftz.f32 %0, %1;" : "=f"(r) : "f"(x)); return r;
}
__device__ __forceinline__ float sqrtaf(float x) {
    float r; asm("sqrt.approx.ftz.f32 %0, %1;" : "=f"(r) : "f"(x)); return r;
}

__global__ __launch_bounds__(THREADS, 6)
void gib_kernel(const float* __restrict__ points,
                const float* __restrict__ q_coords,
                const int*   __restrict__ support_idxs,
                const float* __restrict__ cy_p,
                const float* __restrict__ cone_p,
                const float* __restrict__ disk_p,
                const float* __restrict__ ellip_p,
                const float* __restrict__ lambdas,
                float* __restrict__ out)
{
    // ONE record per (query,k), read warp-uniform: (r2, rx2, s, rz)
    __shared__ float4 sPts[WARPS_PER_BLOCK][Q_PER_WARP][KP];      // ~8.4 KB
    // lamT4[g4*16 + j] = {lam[4g4][j], lam[4g4+1][j], lam[4g4+2][j], lam[4g4+3][j]}/K
    __shared__ float4 lamT4[256];                                  // 4 KB
    __shared__ __align__(16) float meanS[Q_PER_BLOCK * RPAD];      // 4.3 KB

    const int tid   = threadIdx.x;
    const int lane  = tid & 31;
    const int wslot = tid >> 5;
    const int qbase = blockIdx.x * Q_PER_BLOCK;
    const int qA    = qbase + wslot * 2;

    // ---- cooperative packed-transposed lambda load (once per block) ----
    {
        const float invK = 1.f / (float)Kc;
        int g4 = tid >> 4;          // 0..15
        int j  = tid & 15;          // 0..15
        float4 v;
        v.x = lambdas[(4 * g4 + 0) * 16 + j] * invK;
        v.y = lambdas[(4 * g4 + 1) * 16 + j] * invK;
        v.z = lambdas[(4 * g4 + 2) * 16 + j] * invK;
        v.w = lambdas[(4 * g4 + 3) * 16 + j] * invK;
        lamT4[g4 * 16 + j] = v;
    }

    // ---- per-lane gib constants (uniform instruction stream) ----
    // quad gib (g0=lane):  t = p1a*r2 + p1b*s + p2*rz + p3 ; contrib = 2^(-t*t)
    //   lane<16  cyl : p1a=s0, p1b=0,  p2=0,      p3=-s0*a^2
    //   lane>=16 cone: p1a=0,  p1b=s0, p2=-s0*a,  p3=0
    // lin gib (g1=lane+32): a1 = e1*rx2 + e2*r2 + e3*rz2 ; contrib = 2^a1
    float p1a, p1b, p2, p3, e1, e2, e3;
    if (lane < 16) {
        float a  = cy_p[lane * 2 + 0];
        float sg = cy_p[lane * 2 + 1];
        float s0 = sqrtf(LOG2E_F / (2.f * sg * sg + EPSV));
        p1a = s0; p1b = 0.f; p2 = 0.f; p3 = -s0 * a * a;
        float d0 = disk_p[lane * 2 + 0];
        float d1 = disk_p[lane * 2 + 1];
        e1 = 0.f;
        e2 = -LOG2E_F / (d0 * d0 + EPSV);
        e3 = -LOG2E_F / (d1 * d1 + EPSV);
    } else {
        int j = lane - 16;
        float a  = cone_p[j * 2 + 0];
        float sg = cone_p[j * 2 + 1];
        float s0 = sqrtf(LOG2E_F / (2.f * sg * sg + EPSV));
        p1a = 0.f; p1b = s0; p2 = -s0 * a; p3 = 0.f;
        float x0 = ellip_p[j * 3 + 0];
        float x1 = ellip_p[j * 3 + 1];
        float x2 = ellip_p[j * 3 + 2];
        float qx = -LOG2E_F / (x0 * x0 + EPSV);
        float qy = -LOG2E_F / (x1 * x1 + EPSV);
        e1 = qx - qy;                       // on rx2
        e2 = qy;                            // on r2
        e3 = -LOG2E_F / (x2 * x2 + EPSV);   // on rz2
    }

    // ---- gather: lane k loads support point k for both queries ----
    // point load via 2x LDG.64 (parity select) instead of 3x scattered LDG.32
    #pragma unroll
    for (int qq = 0; qq < Q_PER_WARP; qq++) {
        int q = qA + qq;
        const float* qc = q_coords + q * 3;
        float qx = __ldg(qc + 0);
        float qy = __ldg(qc + 1);
        float qz = __ldg(qc + 2);
        int   idx = __ldg(support_idxs + q * Kc + lane);
        int   b   = q >> 13;                          // q / Mc
        unsigned pidx = ((unsigned)b << 16) + (unsigned)idx;   // b*Nc + idx
        unsigned offb = pidx * 12u;                   // byte offset, parity = idx&1
        const char* pb = (const char*)points + (offb & ~7u);
        float2 lo = __ldg((const float2*)pb);
        float2 hi = __ldg((const float2*)(pb + 8));
        bool odd = (idx & 1);
        float px = odd ? lo.y : lo.x;
        float py = odd ? hi.x : lo.y;
        float pz = odd ? hi.y : hi.x;
        float rx = px - qx;
        float ry = py - qy;
        float rz = pz - qz;
        float rx2 = rx * rx;
        float r2  = fmaf(ry, ry, rx2);
        float s   = sqrtaf(r2 + EPSV);
        sPts[wslot][qq][lane] = make_float4(r2, rx2, s, rz);
    }
    __syncwarp();

    const float4* vA = sPts[wslot][0];
    const float4* vB = sPts[wslot][1];

    float acc0A = 0.f, acc1A = 0.f, acc0B = 0.f, acc1B = 0.f;
    #pragma unroll 8
    for (int k = 0; k < Kc; k++) {
        float4 a = vA[k];                 // warp-uniform LDS.128 -> broadcast
        float4 b = vB[k];

        float tA = fmaf(p1a, a.x, fmaf(p1b, a.z, fmaf(p2, a.w, p3)));
        float tB = fmaf(p1a, b.x, fmaf(p1b, b.z, fmaf(p2, b.w, p3)));
        float zA = a.w * a.w;
        float zB = b.w * b.w;
        float aA = fmaf(e1, a.y, fmaf(e2, a.x, e3 * zA));
        float aB = fmaf(e1, b.y, fmaf(e2, b.x, e3 * zB));

        acc0A += ex2f(-tA * tA);
        acc0B += ex2f(-tB * tB);
        acc1A += ex2f(aA);
        acc1B += ex2f(aB);
    }

    // publish the 64 gib means for both queries
    {
        int qqA = wslot * 2, qqB = qqA + 1;
        meanS[qqA * RPAD + lane]      = acc0A;
        meanS[qqA * RPAD + lane + 32] = acc1A;
        meanS[qqB * RPAD + lane]      = acc0B;
        meanS[qqB * RPAD + lane + 32] = acc1B;
    }
    __syncthreads();

    // ---- block-cooperative epilogue: 16 queries x 16 observers ----
    {
        int qq = tid >> 4;
        int j  = tid & 15;
        const float4* mrow = reinterpret_cast<const float4*>(&meanS[qq * RPAD]);
        float acc = 0.f;
        #pragma unroll
        for (int g4 = 0; g4 < 16; g4++) {
            float4 m = mrow[g4];          // uniform per 16-thread group
            float4 l = lamT4[g4 * 16 + j];// consecutive float4 -> conflict-free
            acc += m.x * l.x + m.y * l.y + m.z * l.z + m.w * l.w;
        }
        out[(size_t)(qbase + qq) * 16 + j] = acc;   // fully coalesced
    }
}

extern "C" void kernel_launch(void* const* d_in, const int* in_sizes, int n_in,
                              void* d_out, int out_size)
{
    // metadata order: points, q_coords, support_idxs, mc_points (unused),
    //                 cy_params, cone_params, disk_params, ellip_params, lambdas
    const float* points       = (const float*)d_in[0];
    const float* q_coords     = (const float*)d_in[1];
    const int*   support_idxs = (const int*)  d_in[2];
    const float* cy_params    = (const float*)d_in[4];
    const float* cone_params  = (const float*)d_in[5];
    const float* disk_params  = (const float*)d_in[6];
    const float* ellip_params = (const float*)d_in[7];
    const float* lambdas      = (const float*)d_in[8];
    float* out = (float*)d_out;

    gib_kernel<<<GRID_BLOCKS, THREADS>>>(points, q_coords, support_idxs,
                                         cy_params, cone_params, disk_params,
                                         ellip_params, lambdas, out);
}